// round 1
// baseline (speedup 1.0000x reference)
#include <cuda_runtime.h>
#include <math.h>
#include <stdint.h>

#define B_    256
#define T_    100
#define IN_   784
#define H_    200
#define R_    4
#define N_    128
#define D_    40
#define NCLS  5
#define G4H   800   // 4*H
#define RD    160   // R*D
#define MSTRIDE 41  // D padded to odd stride for bank-conflict-free columns

#define BPB   2     // batch elements per block (recurrent kernel)
#define NBLK  (B_/BPB)
#define THREADS 256

// ---------------- device scratch (no cudaMalloc allowed) ----------------
__device__ float g_G[B_*T_*G4H];       // precomputed x@Wih.T + bih  (81.9MB)
__device__ float g_WhhT[H_*G4H];       // [k=200][j=800]
__device__ float g_WkeyT[H_*RD];       // [k=200][j=160]
__device__ float g_WaddT[H_*RD];
__device__ float g_WrhT[RD*H_];        // [k=160][j=200]

// ---------------- weight transpose prep ----------------
__global__ void prep_weights(const float* __restrict__ Whh,
                             const float* __restrict__ Wkey,
                             const float* __restrict__ Wadd,
                             const float* __restrict__ Wrh) {
    int i = blockIdx.x * 256 + threadIdx.x;
    if (i < 160000) {                       // WhhT[k][j] = Whh[j][k]
        int k = i / 800, j = i % 800;
        g_WhhT[i] = Whh[j * 200 + k];
    } else if (i < 192000) {                // WkeyT
        int z = i - 160000; int k = z / 160, j = z % 160;
        g_WkeyT[z] = Wkey[j * 200 + k];
    } else if (i < 224000) {                // WaddT
        int z = i - 192000; int k = z / 160, j = z % 160;
        g_WaddT[z] = Wadd[j * 200 + k];
    } else if (i < 256000) {                // WrhT[k][j] = Wrh[j][k]
        int z = i - 224000; int k = z / 200, j = z % 200;
        g_WrhT[z] = Wrh[j * 160 + k];
    }
}

// ---------------- big input GEMM: G = x @ Wih^T + bih ----------------
// C[25600][800] = A[25600][784] * B[800][784]^T ; both K-major (NT gemm)
#define GBM 128
#define GBN 64
#define GBK 16
__global__ __launch_bounds__(256) void gemm_gates_x(
    const float* __restrict__ X, const float* __restrict__ Wih,
    const float* __restrict__ bih) {
    __shared__ float As[GBK][GBM + 1];
    __shared__ float Bs[GBK][GBN + 1];
    const int tid = threadIdx.x;
    const int m0 = blockIdx.y * GBM;
    const int n0 = blockIdx.x * GBN;
    const int tx = tid & 15, ty = tid >> 4;

    float acc[8][4];
#pragma unroll
    for (int i = 0; i < 8; i++)
#pragma unroll
        for (int j = 0; j < 4; j++) acc[i][j] = 0.f;

    const int ar = tid >> 1, ac0 = (tid & 1) * 8;      // A: 128 rows x 16
    const int br = tid >> 2, bc0 = (tid & 3) * 4;      // B: 64 rows x 16
    const int bgn = n0 + br;

    for (int kt = 0; kt < IN_; kt += GBK) {
        {
            const float* src = X + (size_t)(m0 + ar) * IN_ + kt + ac0;
            float4 v0 = *(const float4*)src;
            float4 v1 = *(const float4*)(src + 4);
            As[ac0 + 0][ar] = v0.x; As[ac0 + 1][ar] = v0.y;
            As[ac0 + 2][ar] = v0.z; As[ac0 + 3][ar] = v0.w;
            As[ac0 + 4][ar] = v1.x; As[ac0 + 5][ar] = v1.y;
            As[ac0 + 6][ar] = v1.z; As[ac0 + 7][ar] = v1.w;
        }
        {
            float4 v = make_float4(0.f, 0.f, 0.f, 0.f);
            if (bgn < G4H) v = *(const float4*)(Wih + (size_t)bgn * IN_ + kt + bc0);
            Bs[bc0 + 0][br] = v.x; Bs[bc0 + 1][br] = v.y;
            Bs[bc0 + 2][br] = v.z; Bs[bc0 + 3][br] = v.w;
        }
        __syncthreads();
#pragma unroll
        for (int k = 0; k < GBK; k++) {
            float ra[8], rb[4];
#pragma unroll
            for (int im = 0; im < 8; im++) ra[im] = As[k][ty + 16 * im];
#pragma unroll
            for (int jn = 0; jn < 4; jn++) rb[jn] = Bs[k][tx + 16 * jn];
#pragma unroll
            for (int im = 0; im < 8; im++)
#pragma unroll
                for (int jn = 0; jn < 4; jn++) acc[im][jn] += ra[im] * rb[jn];
        }
        __syncthreads();
    }
#pragma unroll
    for (int im = 0; im < 8; im++) {
        int gm = m0 + ty + 16 * im;
#pragma unroll
        for (int jn = 0; jn < 4; jn++) {
            int gn = n0 + tx + 16 * jn;
            if (gn < G4H) g_G[(size_t)gm * G4H + gn] = acc[im][jn] + bih[gn];
        }
    }
}

// ---------------- recurrent kernel: one block owns BPB batch elements for all T ----------------
struct BS {
    unsigned long long red64[4];
    int lu[4];
    float M[N_ * MSTRIDE];
    float h[H_];
    float c[H_];
    float r[RD];
    float key[RD];
    float add[RD];
    float gates[G4H];
    float wr[R_ * N_];
    float wu[N_];
    float ww[R_ * N_];
    float wwsum[N_];
    float Ksm[R_ * N_];
    float m2[N_];
    float wlu[N_];
    float key2[R_];
    float sig;
    float red0[8];
    float red1[8];
};

__device__ __forceinline__ float sigmoidf_(float x) { return 1.f / (1.f + expf(-x)); }

__global__ __launch_bounds__(THREADS) void mann_recurrent(
    const float* __restrict__ bkey, const float* __restrict__ badd,
    const float* __restrict__ Wsig, const float* __restrict__ bsig,
    const float* __restrict__ Who,  const float* __restrict__ bho,
    const float* __restrict__ Wro,  const float* __restrict__ bro,
    const float* __restrict__ brh,  const float* __restrict__ bhh,
    float* __restrict__ out) {
    extern __shared__ char smemraw[];
    BS* S = reinterpret_cast<BS*>(smemraw);
    const int tid = threadIdx.x;
    const int blk = blockIdx.x;

    // zero initial state
    for (int b = 0; b < BPB; b++) {
        BS& s = S[b];
        for (int i = tid; i < N_ * MSTRIDE; i += THREADS) s.M[i] = 0.f;
        for (int i = tid; i < H_; i += THREADS) { s.h[i] = 0.f; s.c[i] = 0.f; }
        for (int i = tid; i < RD; i += THREADS) s.r[i] = 0.f;
        for (int i = tid; i < R_ * N_; i += THREADS) s.wr[i] = 0.f;
        for (int i = tid; i < N_; i += THREADS) s.wu[i] = 0.f;
    }
    __syncthreads();

    for (int t = 0; t < T_; t++) {
        // ---- phase 1: h += r @ WrhT + brh ----
        if (tid < H_) {
            float a0 = 0.f, a1 = 0.f;
#pragma unroll 8
            for (int k = 0; k < RD; k++) {
                float w = g_WrhT[k * H_ + tid];
                a0 += S[0].r[k] * w;
                a1 += S[1].r[k] * w;
            }
            float bb = brh[tid];
            S[0].h[tid] += a0 + bb;
            S[1].h[tid] += a1 + bb;
        }
        __syncthreads();

        // ---- phase 2: gates = G + h @ WhhT + bhh ----
        {
            float acc0[4] = {0.f, 0.f, 0.f, 0.f};
            float acc1[4] = {0.f, 0.f, 0.f, 0.f};
#pragma unroll 4
            for (int k = 0; k < H_; k++) {
                float h0 = S[0].h[k], h1 = S[1].h[k];
                const float* Wk = g_WhhT + k * G4H;
                float w0 = Wk[tid];
                float w1 = Wk[tid + 256];
                float w2 = Wk[tid + 512];
                acc0[0] += w0 * h0; acc1[0] += w0 * h1;
                acc0[1] += w1 * h0; acc1[1] += w1 * h1;
                acc0[2] += w2 * h0; acc1[2] += w2 * h1;
                if (tid < 32) {
                    float w3 = Wk[tid + 768];
                    acc0[3] += w3 * h0; acc1[3] += w3 * h1;
                }
            }
            const float* G0 = g_G + ((size_t)(blk * BPB + 0) * T_ + t) * G4H;
            const float* G1 = g_G + ((size_t)(blk * BPB + 1) * T_ + t) * G4H;
#pragma unroll
            for (int m = 0; m < 3; m++) {
                int j = tid + 256 * m;
                float bb = bhh[j];
                S[0].gates[j] = G0[j] + acc0[m] + bb;
                S[1].gates[j] = G1[j] + acc1[m] + bb;
            }
            if (tid < 32) {
                int j = 768 + tid;
                float bb = bhh[j];
                S[0].gates[j] = G0[j] + acc0[3] + bb;
                S[1].gates[j] = G1[j] + acc1[3] + bb;
            }
        }
        __syncthreads();

        // ---- phase 3: LSTM pointwise ----
        if (tid < H_) {
#pragma unroll
            for (int b = 0; b < BPB; b++) {
                BS& s = S[b];
                float ig = sigmoidf_(s.gates[tid]);
                float fg = sigmoidf_(s.gates[200 + tid]);
                float gg = tanhf(s.gates[400 + tid]);
                float og = sigmoidf_(s.gates[600 + tid]);
                float ct = fg * s.c[tid] + ig * gg;
                s.c[tid] = ct;
                s.h[tid] = og * tanhf(ct);
            }
        }
        __syncthreads();

        // ---- phase 4: key/add projections + sigma partials ----
        if (tid < RD) {
            float k0 = 0.f, k1 = 0.f, a0 = 0.f, a1 = 0.f;
#pragma unroll 4
            for (int k = 0; k < H_; k++) {
                float h0 = S[0].h[k], h1 = S[1].h[k];
                float wk = g_WkeyT[k * RD + tid];
                float wa = g_WaddT[k * RD + tid];
                k0 += wk * h0; k1 += wk * h1;
                a0 += wa * h0; a1 += wa * h1;
            }
            S[0].key[tid] = k0 + bkey[tid]; S[1].key[tid] = k1 + bkey[tid];
            S[0].add[tid] = a0 + badd[tid]; S[1].add[tid] = a1 + badd[tid];
        }
        {
            float p0 = 0.f, p1 = 0.f;
            if (tid < H_) {
                float w = Wsig[tid];
                p0 = S[0].h[tid] * w;
                p1 = S[1].h[tid] * w;
            }
#pragma unroll
            for (int o = 16; o > 0; o >>= 1) {
                p0 += __shfl_down_sync(0xffffffffu, p0, o);
                p1 += __shfl_down_sync(0xffffffffu, p1, o);
            }
            if ((tid & 31) == 0) {
                S[0].red0[tid >> 5] = p0;
                S[0].red1[tid >> 5] = p1;
            }
        }
        __syncthreads();
        if (tid == 0) { float s = 0.f; for (int w = 0; w < 8; w++) s += S[0].red0[w]; S[0].sig = s + bsig[0]; }
        if (tid == 1) { float s = 0.f; for (int w = 0; w < 8; w++) s += S[0].red1[w]; S[1].sig = s + bsig[0]; }
        if (tid >= 8 && tid < 16) {
            int b = (tid - 8) >> 2, r = (tid - 8) & 3;
            float s = 0.f;
#pragma unroll
            for (int d = 0; d < D_; d++) { float v = S[b].key[r * D_ + d]; s += v * v; }
            S[b].key2[r] = s;
        }
        __syncthreads();

        // ---- phase 5: stable 4-smallest selection over wu ----
        {
            int half = tid >> 7;
            int ht = tid & 127;
            BS& s = S[half];
            unsigned long long kv;
            {
                float v = s.wu[ht];
                unsigned u = __float_as_uint(v);
                u = (u & 0x80000000u) ? ~u : (u | 0x80000000u);
                kv = ((unsigned long long)u << 32) | (unsigned)ht;
            }
#pragma unroll
            for (int ss = 0; ss < 4; ss++) {
                unsigned long long m = kv;
#pragma unroll
                for (int o = 16; o > 0; o >>= 1) {
                    unsigned long long x = __shfl_down_sync(0xffffffffu, m, o);
                    if (x < m) m = x;
                }
                if ((tid & 31) == 0) s.red64[ht >> 5] = m;
                __syncthreads();
                if (ht == 0) {
                    unsigned long long mm = s.red64[0];
#pragma unroll
                    for (int w = 1; w < 4; w++) if (s.red64[w] < mm) mm = s.red64[w];
                    s.lu[ss] = (int)(mm & 0xffffffffull);
                }
                __syncthreads();
                if (ht == s.lu[ss]) kv = 0xffffffffffffffffull;
            }
            float wl = (ht == s.lu[0] || ht == s.lu[1] || ht == s.lu[2] || ht == s.lu[3]) ? 1.f : 0.f;
            s.wlu[ht] = wl;
        }
        __syncthreads();

        // ---- phase 6a: ww = sig*wr + (1-sig)*wlu ----
        for (int e = tid; e < BPB * R_ * N_; e += THREADS) {
            int b = e >> 9; int rn = e & 511; int n = rn & 127;
            BS& s = S[b];
            float sg = s.sig;
            s.ww[rn] = sg * s.wr[rn] + (1.f - sg) * s.wlu[n];
        }
        __syncthreads();

        // ---- phase 6b: M update + m2 + wwsum (one thread per (b,n)) ----
        {
            int b = tid >> 7, n = tid & 127;
            BS& s = S[b];
            float wl = s.wlu[n];
            float w0 = s.ww[n], w1 = s.ww[128 + n], w2 = s.ww[256 + n], w3 = s.ww[384 + n];
            s.wwsum[n] = w0 + w1 + w2 + w3;
            float m2acc = 0.f;
#pragma unroll
            for (int d = 0; d < D_; d++) {
                float mv = s.M[n * MSTRIDE + d] * wl
                         + w0 * s.add[d] + w1 * s.add[40 + d]
                         + w2 * s.add[80 + d] + w3 * s.add[120 + d];
                s.M[n * MSTRIDE + d] = mv;
                m2acc += mv * mv;
            }
            s.m2[n] = m2acc;
        }
        __syncthreads();

        // ---- phase 7: cosine similarity K ----
        for (int e = tid; e < BPB * R_ * N_; e += THREADS) {
            int b = e >> 9, rn = e & 511, r = rn >> 7, n = rn & 127;
            BS& s = S[b];
            float dot = 0.f;
#pragma unroll
            for (int d = 0; d < D_; d++) dot += s.key[r * D_ + d] * s.M[n * MSTRIDE + d];
            s.Ksm[rn] = dot / sqrtf(s.key2[r] * s.m2[n] + 1e-6f);
        }
        __syncthreads();

        // ---- phase 8: softmax over n (warp per (b,r)) ----
        {
            int w = tid >> 5, lane = tid & 31;
            int b = w >> 2, r = w & 3;
            BS& s = S[b];
            float v0 = s.Ksm[r * N_ + lane];
            float v1 = s.Ksm[r * N_ + 32 + lane];
            float v2 = s.Ksm[r * N_ + 64 + lane];
            float v3 = s.Ksm[r * N_ + 96 + lane];
            float mx = fmaxf(fmaxf(v0, v1), fmaxf(v2, v3));
#pragma unroll
            for (int o = 16; o > 0; o >>= 1) mx = fmaxf(mx, __shfl_xor_sync(0xffffffffu, mx, o));
            float e0 = expf(v0 - mx), e1 = expf(v1 - mx), e2 = expf(v2 - mx), e3 = expf(v3 - mx);
            float su = e0 + e1 + e2 + e3;
#pragma unroll
            for (int o = 16; o > 0; o >>= 1) su += __shfl_xor_sync(0xffffffffu, su, o);
            float inv = 1.f / su;
            s.wr[r * N_ + lane]      = e0 * inv;
            s.wr[r * N_ + 32 + lane] = e1 * inv;
            s.wr[r * N_ + 64 + lane] = e2 * inv;
            s.wr[r * N_ + 96 + lane] = e3 * inv;
        }
        __syncthreads();

        // ---- phase 9: wu update ----
        {
            int b = tid >> 7, n = tid & 127;
            BS& s = S[b];
            s.wu[n] = 0.95f * s.wu[n]
                    + (s.wr[n] + s.wr[128 + n] + s.wr[256 + n] + s.wr[384 + n])
                    + s.wwsum[n];
        }
        // ---- phase 10: r_t = wr @ M ----
        for (int e = tid; e < BPB * RD; e += THREADS) {
            int b = (e >= RD) ? 1 : 0;
            int rd = e - b * RD;
            int r = rd / D_, d = rd % D_;
            BS& s = S[b];
            float dot = 0.f;
#pragma unroll 8
            for (int n = 0; n < N_; n++) dot += s.wr[r * N_ + n] * s.M[n * MSTRIDE + d];
            s.r[rd] = dot;
        }
        __syncthreads();

        // ---- phase 11: output projection ----
        {
            int w = tid >> 5, lane = tid & 31;
            for (int pair = w; pair < BPB * NCLS; pair += 8) {
                int b = pair / NCLS, cls = pair % NCLS;
                BS& s = S[b];
                float acc = 0.f;
                for (int k = lane; k < H_; k += 32) acc += s.h[k] * Who[cls * H_ + k];
                for (int k = lane; k < RD; k += 32) acc += s.r[k] * Wro[cls * RD + k];
#pragma unroll
                for (int o = 16; o > 0; o >>= 1) acc += __shfl_down_sync(0xffffffffu, acc, o);
                if (lane == 0)
                    out[((size_t)(blk * BPB + b) * T_ + t) * NCLS + cls] = acc + bho[cls] + bro[cls];
            }
        }
        __syncthreads();
    }
}

// ---------------- launch ----------------
extern "C" void kernel_launch(void* const* d_in, const int* in_sizes, int n_in,
                              void* d_out, int out_size) {
    const float* x    = (const float*)d_in[0];
    const float* Wkey = (const float*)d_in[1];
    const float* bkey = (const float*)d_in[2];
    const float* Wadd = (const float*)d_in[3];
    const float* badd = (const float*)d_in[4];
    const float* Wsig = (const float*)d_in[5];
    const float* bsig = (const float*)d_in[6];
    const float* Who  = (const float*)d_in[7];
    const float* bho  = (const float*)d_in[8];
    const float* Wro  = (const float*)d_in[9];
    const float* bro  = (const float*)d_in[10];
    const float* Wrh  = (const float*)d_in[11];
    const float* brh  = (const float*)d_in[12];
    const float* Wih  = (const float*)d_in[13];
    const float* bih  = (const float*)d_in[14];
    const float* Whh  = (const float*)d_in[15];
    const float* bhh  = (const float*)d_in[16];
    float* out = (float*)d_out;

    prep_weights<<<1000, 256>>>(Whh, Wkey, Wadd, Wrh);
    gemm_gates_x<<<dim3((G4H + GBN - 1) / GBN, B_ * T_ / GBM), 256>>>(x, Wih, bih);

    size_t shmem = 2 * sizeof(BS);
    cudaFuncSetAttribute(mann_recurrent, cudaFuncAttributeMaxDynamicSharedMemorySize, (int)shmem);
    mann_recurrent<<<NBLK, THREADS, shmem>>>(bkey, badd, Wsig, bsig, Who, bho,
                                             Wro, bro, brh, bhh, out);
}

// round 3
// speedup vs baseline: 1.7492x; 1.7492x over previous
#include <cuda_runtime.h>
#include <math.h>
#include <stdint.h>

#define B_    256
#define T_    100
#define IN_   784
#define H_    200
#define R_    4
#define N_    128
#define D_    40
#define NCLS  5
#define G4H   800   // 4*H
#define RD    160   // R*D
#define MSTRIDE 41  // D padded for bank-conflict-free column access

#define BPB   2
#define NBLK  (B_/BPB)
#define THREADS 512

// ---------------- device scratch ----------------
__device__ float g_G[B_*T_*G4H];       // x@Wih.T + bih
__device__ float g_WhhT[H_*G4H];       // [k=200][j=800]
__device__ float g_WkaT[H_*320];       // [k=200][ key(160) | add(160) ]
__device__ float g_WrhT[RD*H_];        // [k=160][j=200]

// ---------------- weight transpose prep ----------------
__global__ void prep_weights(const float* __restrict__ Whh,
                             const float* __restrict__ Wkey,
                             const float* __restrict__ Wadd,
                             const float* __restrict__ Wrh) {
    int i = blockIdx.x * 256 + threadIdx.x;
    if (i < 160000) {                       // WhhT[k][j] = Whh[j][k]
        int k = i / 800, j = i % 800;
        g_WhhT[i] = Whh[j * 200 + k];
    } else if (i < 224000) {                // WkaT[k][j]
        int z = i - 160000; int k = z / 320, j = z % 320;
        g_WkaT[z] = (j < 160) ? Wkey[j * 200 + k] : Wadd[(j - 160) * 200 + k];
    } else if (i < 256000) {                // WrhT[k][j] = Wrh[j][k]
        int z = i - 224000; int k = z / 200, j = z % 200;
        g_WrhT[z] = Wrh[j * 160 + k];
    }
}

// ---------------- big input GEMM: G = x @ Wih^T + bih ----------------
#define GBM 128
#define GBN 128
#define GBK 16
__global__ __launch_bounds__(256) void gemm_gates_x(
    const float* __restrict__ X, const float* __restrict__ Wih,
    const float* __restrict__ bih) {
    __shared__ float As[GBK][GBM + 4];
    __shared__ float Bs[GBK][GBN + 4];
    const int tid = threadIdx.x;
    const int m0 = blockIdx.y * GBM;
    const int n0 = blockIdx.x * GBN;
    const int tx = tid & 15, ty = tid >> 4;

    float acc[8][8];
#pragma unroll
    for (int i = 0; i < 8; i++)
#pragma unroll
        for (int j = 0; j < 8; j++) acc[i][j] = 0.f;

    const int ar = tid >> 1, ac = (tid & 1) * 8;
    const int bn = n0 + ar;

    for (int kt = 0; kt < IN_; kt += GBK) {
        {
            const float* src = X + (size_t)(m0 + ar) * IN_ + kt + ac;
            float4 v0 = *(const float4*)src;
            float4 v1 = *(const float4*)(src + 4);
            As[ac + 0][ar] = v0.x; As[ac + 1][ar] = v0.y;
            As[ac + 2][ar] = v0.z; As[ac + 3][ar] = v0.w;
            As[ac + 4][ar] = v1.x; As[ac + 5][ar] = v1.y;
            As[ac + 6][ar] = v1.z; As[ac + 7][ar] = v1.w;
        }
        {
            float4 v0 = make_float4(0.f,0.f,0.f,0.f), v1 = v0;
            if (bn < G4H) {
                const float* src = Wih + (size_t)bn * IN_ + kt + ac;
                v0 = *(const float4*)src;
                v1 = *(const float4*)(src + 4);
            }
            Bs[ac + 0][ar] = v0.x; Bs[ac + 1][ar] = v0.y;
            Bs[ac + 2][ar] = v0.z; Bs[ac + 3][ar] = v0.w;
            Bs[ac + 4][ar] = v1.x; Bs[ac + 5][ar] = v1.y;
            Bs[ac + 6][ar] = v1.z; Bs[ac + 7][ar] = v1.w;
        }
        __syncthreads();
#pragma unroll
        for (int k = 0; k < GBK; k++) {
            float ra[8], rb[8];
#pragma unroll
            for (int i = 0; i < 8; i++) ra[i] = As[k][ty + 16 * i];
#pragma unroll
            for (int j = 0; j < 8; j++) rb[j] = Bs[k][tx + 16 * j];
#pragma unroll
            for (int i = 0; i < 8; i++)
#pragma unroll
                for (int j = 0; j < 8; j++) acc[i][j] += ra[i] * rb[j];
        }
        __syncthreads();
    }
    float bihr[8];
#pragma unroll
    for (int j = 0; j < 8; j++) {
        int gn = n0 + tx + 16 * j;
        bihr[j] = (gn < G4H) ? bih[gn] : 0.f;
    }
#pragma unroll
    for (int i = 0; i < 8; i++) {
        size_t base = (size_t)(m0 + ty + 16 * i) * G4H;
#pragma unroll
        for (int j = 0; j < 8; j++) {
            int gn = n0 + tx + 16 * j;
            if (gn < G4H) g_G[base + gn] = acc[i][j] + bihr[j];
        }
    }
}

// ---------------- recurrent kernel ----------------
// NOTE: alignas(16) + explicit pad so sizeof(BS) is a multiple of 16 bytes;
// S[1] must keep float4-aligned members (R2 failed here with misaligned address).
struct __align__(16) BS {
    float M[N_ * MSTRIDE];   // 5248
    float h[H_];             // 200
    float c[H_];             // 200
    float r[RD];             // 160
    float key[RD];           // 160
    float add[RD];           // 160
    float gates[G4H];        // 800  (offset 6128 floats -> 16B aligned)
    float wr[R_ * N_];       // 512
    float wu[N_];            // 128
    float wwsum[N_];         // 128
    float Ksm[R_ * N_];      // 512
    float m2[N_];            // 128
    float wlu[N_];           // 128
    float key2[R_];          // 4
    float sig;               // 1
    float pad_[3];           // -> 8472 floats total = 33888 bytes (mult of 16)
};
#define BSF (sizeof(BS)/4)

__device__ __forceinline__ float sigmoidf_(float x) { return 1.f / (1.f + expf(-x)); }

__global__ __launch_bounds__(THREADS) void mann_recurrent(
    const float* __restrict__ bkey, const float* __restrict__ badd,
    const float* __restrict__ Wsig, const float* __restrict__ bsig,
    const float* __restrict__ Who,  const float* __restrict__ bho,
    const float* __restrict__ Wro,  const float* __restrict__ bro,
    const float* __restrict__ brh,  const float* __restrict__ bhh,
    float* __restrict__ out) {
    extern __shared__ float smemf[];
    BS* S = reinterpret_cast<BS*>(smemf);
    float* Pbuf = smemf + 2 * BSF;        // 3200 floats of partial-sum scratch
    float* sWrh = Pbuf + 3200;            // 32000 floats: WrhT pinned in SMEM

    const int tid = threadIdx.x;
    const int blk = blockIdx.x;
    const int wid = tid >> 5, lane = tid & 31;

    // init: zero state, load WrhT into SMEM
    for (int b = 0; b < BPB; b++) {
        BS& s = S[b];
        for (int i = tid; i < N_ * MSTRIDE; i += THREADS) s.M[i] = 0.f;
        for (int i = tid; i < H_; i += THREADS) { s.h[i] = 0.f; s.c[i] = 0.f; }
        for (int i = tid; i < RD; i += THREADS) s.r[i] = 0.f;
        for (int i = tid; i < R_ * N_; i += THREADS) s.wr[i] = 0.f;
        for (int i = tid; i < N_; i += THREADS) s.wu[i] = 0.f;
    }
    for (int i = tid; i < RD * H_; i += THREADS) sWrh[i] = g_WrhT[i];
    __syncthreads();

    for (int t = 0; t < T_; t++) {
        // ---- prefetch G row (DRAM, consumed in phase 2b) ----
        float4 Greg = make_float4(0.f,0.f,0.f,0.f);
        int p_b = 0, p_j4 = 0;
        if (tid < 400) {
            p_b = tid / 200; p_j4 = tid % 200;
            Greg = *(const float4*)(g_G + ((size_t)(blk * BPB + p_b) * T_ + t) * G4H + 4 * p_j4);
        }

        // ---- phase 1: h += r @ WrhT + brh (SMEM weights) ----
        if (tid < 400) {
            int b = p_b, j = tid % 200;
            const float* rr = S[b].r;
            float acc = 0.f;
#pragma unroll 8
            for (int k = 0; k < RD; k++) acc += rr[k] * sWrh[k * 200 + j];
            S[b].h[j] += acc + brh[j];
        }
        __syncthreads();

        // ---- phase 2a: gates partials, k-split ----
        if (tid < 400) {
            int g = tid / 200, j = (tid % 200) * 4;
            int kb = g * 100;
            float4 a0 = make_float4(0.f,0.f,0.f,0.f);
            float4 a1 = a0;
#pragma unroll 4
            for (int kk = 0; kk < 100; kk++) {
                int k = kb + kk;
                float4 w = *(const float4*)(g_WhhT + (size_t)k * G4H + j);
                float h0 = S[0].h[k], h1 = S[1].h[k];
                a0.x += w.x * h0; a0.y += w.y * h0; a0.z += w.z * h0; a0.w += w.w * h0;
                a1.x += w.x * h1; a1.y += w.y * h1; a1.z += w.z * h1; a1.w += w.w * h1;
            }
            *(float4*)&Pbuf[(g * 2 + 0) * G4H + j] = a0;
            *(float4*)&Pbuf[(g * 2 + 1) * G4H + j] = a1;
        }
        __syncthreads();

        // ---- phase 2b: combine partials + G + bhh -> gates ----
        if (tid < 400) {
            int b = p_b, j = p_j4 * 4;
            float4 q0 = *(const float4*)&Pbuf[(0 * 2 + b) * G4H + j];
            float4 q1 = *(const float4*)&Pbuf[(1 * 2 + b) * G4H + j];
            float4 bb = *(const float4*)(bhh + j);
            float4 res;
            res.x = Greg.x + q0.x + q1.x + bb.x;
            res.y = Greg.y + q0.y + q1.y + bb.y;
            res.z = Greg.z + q0.z + q1.z + bb.z;
            res.w = Greg.w + q0.w + q1.w + bb.w;
            *(float4*)&S[b].gates[j] = res;
        }
        __syncthreads();

        // ---- phase 3: LSTM pointwise ----
        if (tid < 400) {
            int b = p_b, i = tid % 200;
            BS& s = S[b];
            float ig = sigmoidf_(s.gates[i]);
            float fg = sigmoidf_(s.gates[200 + i]);
            float gg = tanhf(s.gates[400 + i]);
            float og = sigmoidf_(s.gates[600 + i]);
            float ct = fg * s.c[i] + ig * gg;
            s.c[i] = ct;
            s.h[i] = og * tanhf(ct);
        }
        __syncthreads();

        // ---- phase 4a: key/add partials (k-split, both b) ; sigma ; LRU selection ----
        if (tid < 320) {
            int g = tid / 160, j2 = tid % 160;
            int kb = g * 100;
            float2 a0 = make_float2(0.f, 0.f), a1 = a0;
#pragma unroll 4
            for (int kk = 0; kk < 100; kk++) {
                int k = kb + kk;
                float2 w = *(const float2*)(g_WkaT + (size_t)k * 320 + 2 * j2);
                float h0 = S[0].h[k], h1 = S[1].h[k];
                a0.x += w.x * h0; a0.y += w.y * h0;
                a1.x += w.x * h1; a1.y += w.y * h1;
            }
            *(float2*)&Pbuf[(g * 2 + 0) * 320 + 2 * j2] = a0;
            *(float2*)&Pbuf[(g * 2 + 1) * 320 + 2 * j2] = a1;
        } else if (wid == 10 || wid == 11) {
            // sigma = h . Wsig + bsig  (one warp per b)
            int b = wid - 10;
            float p = 0.f;
            for (int k = lane; k < H_; k += 32) p += S[b].h[k] * Wsig[k];
#pragma unroll
            for (int o = 16; o > 0; o >>= 1) p += __shfl_xor_sync(0xffffffffu, p, o);
            if (lane == 0) S[b].sig = p + bsig[0];
        } else if (wid == 12 || wid == 13) {
            // stable 4-smallest of wu (one warp per b), sync-free
            int b = wid - 12;
            unsigned long long kv[4];
            float wl[4];
#pragma unroll
            for (int q = 0; q < 4; q++) {
                int n = lane + 32 * q;
                unsigned u = __float_as_uint(S[b].wu[n]);
                u = (u & 0x80000000u) ? ~u : (u | 0x80000000u);
                kv[q] = ((unsigned long long)u << 32) | (unsigned)n;
                wl[q] = 0.f;
            }
#pragma unroll
            for (int ss = 0; ss < 4; ss++) {
                unsigned long long m = kv[0]; int qi = 0;
#pragma unroll
                for (int q = 1; q < 4; q++) if (kv[q] < m) { m = kv[q]; qi = q; }
                unsigned long long wm = m;
#pragma unroll
                for (int o = 16; o > 0; o >>= 1) {
                    unsigned long long x = __shfl_xor_sync(0xffffffffu, wm, o);
                    if (x < wm) wm = x;
                }
                if (m == wm) { wl[qi] = 1.f; kv[qi] = ~0ull; }
            }
#pragma unroll
            for (int q = 0; q < 4; q++) S[b].wlu[lane + 32 * q] = wl[q];
        }
        __syncthreads();

        // ---- phase 4b: combine key/add partials ----
        for (int e = tid; e < 640; e += THREADS) {
            int b = (e >= 320) ? 1 : 0;
            int c = e - b * 320;
            float v = Pbuf[(0 * 2 + b) * 320 + c] + Pbuf[(1 * 2 + b) * 320 + c];
            if (c < 160) S[b].key[c] = v + bkey[c];
            else         S[b].add[c - 160] = v + badd[c - 160];
        }
        __syncthreads();

        // ---- phase 6: M update + wwsum + m2 (ww computed inline) ; key2 ----
        {
            int b = tid >> 8;
            int n = (tid >> 1) & 127;
            int dh = tid & 1;
            BS& s = S[b];
            float sg = s.sig, omsg = 1.f - sg;
            float wl = s.wlu[n];
            float w0 = sg * s.wr[n]       + omsg * wl;
            float w1 = sg * s.wr[128 + n] + omsg * wl;
            float w2 = sg * s.wr[256 + n] + omsg * wl;
            float w3 = sg * s.wr[384 + n] + omsg * wl;
            if (dh == 0) s.wwsum[n] = w0 + w1 + w2 + w3;
            float m2p = 0.f;
            int d0 = dh * 20;
#pragma unroll
            for (int dd = 0; dd < 20; dd++) {
                int d = d0 + dd;
                float mv = s.M[n * MSTRIDE + d] * wl
                         + w0 * s.add[d] + w1 * s.add[40 + d]
                         + w2 * s.add[80 + d] + w3 * s.add[120 + d];
                s.M[n * MSTRIDE + d] = mv;
                m2p += mv * mv;
            }
            m2p += __shfl_xor_sync(0xffffffffu, m2p, 1);
            if (dh == 0) s.m2[n] = m2p;
        }
        if (tid < 8) {
            int b = tid >> 2, r = tid & 3;
            float sum = 0.f;
#pragma unroll
            for (int d = 0; d < D_; d++) { float v = S[b].key[r * 40 + d]; sum += v * v; }
            S[b].key2[r] = sum;
        }
        __syncthreads();

        // ---- phase 7: cosine similarity ----
        for (int e = tid; e < 1024; e += THREADS) {
            int b = e >> 9, rn = e & 511, r = rn >> 7, n = rn & 127;
            BS& s = S[b];
            const float* kp = s.key + r * 40;
            const float* mp = s.M + n * MSTRIDE;
            float dot = 0.f;
#pragma unroll
            for (int d = 0; d < D_; d++) dot += kp[d] * mp[d];
            s.Ksm[rn] = dot / sqrtf(s.key2[r] * s.m2[n] + 1e-6f);
        }
        __syncthreads();

        // ---- phase 8: softmax over n (warp per (b,r)) ----
        if (wid < 8) {
            int b = wid >> 2, r = wid & 3;
            BS& s = S[b];
            float v0 = s.Ksm[r * N_ + lane];
            float v1 = s.Ksm[r * N_ + 32 + lane];
            float v2 = s.Ksm[r * N_ + 64 + lane];
            float v3 = s.Ksm[r * N_ + 96 + lane];
            float mx = fmaxf(fmaxf(v0, v1), fmaxf(v2, v3));
#pragma unroll
            for (int o = 16; o > 0; o >>= 1) mx = fmaxf(mx, __shfl_xor_sync(0xffffffffu, mx, o));
            float e0 = expf(v0 - mx), e1 = expf(v1 - mx), e2 = expf(v2 - mx), e3 = expf(v3 - mx);
            float su = e0 + e1 + e2 + e3;
#pragma unroll
            for (int o = 16; o > 0; o >>= 1) su += __shfl_xor_sync(0xffffffffu, su, o);
            float inv = 1.f / su;
            s.wr[r * N_ + lane]      = e0 * inv;
            s.wr[r * N_ + 32 + lane] = e1 * inv;
            s.wr[r * N_ + 64 + lane] = e2 * inv;
            s.wr[r * N_ + 96 + lane] = e3 * inv;
        }
        __syncthreads();

        // ---- phase 9: wu update ; phase 10: r_t = wr @ M ----
        if (tid < 256) {
            int b = tid >> 7, n = tid & 127;
            BS& s = S[b];
            s.wu[n] = 0.95f * s.wu[n]
                    + (s.wr[n] + s.wr[128 + n] + s.wr[256 + n] + s.wr[384 + n])
                    + s.wwsum[n];
        }
        if (tid < 320) {
            int b = tid / 160, rd = tid % 160;
            int r = rd / 40, d = rd % 40;
            BS& s = S[b];
            const float* wrp = s.wr + r * N_;
            float dot = 0.f;
#pragma unroll 8
            for (int n = 0; n < N_; n++) dot += wrp[n] * s.M[n * MSTRIDE + d];
            s.r[rd] = dot;
        }
        __syncthreads();

        // ---- phase 11: output projection (warp per (b,cls)) ----
        if (wid < 10) {
            int b = wid / 5, cls = wid % 5;
            BS& s = S[b];
            float acc = 0.f;
            for (int k = lane; k < H_; k += 32) acc += s.h[k] * Who[cls * H_ + k];
            for (int k = lane; k < RD; k += 32) acc += s.r[k] * Wro[cls * RD + k];
#pragma unroll
            for (int o = 16; o > 0; o >>= 1) acc += __shfl_down_sync(0xffffffffu, acc, o);
            if (lane == 0)
                out[((size_t)(blk * BPB + b) * T_ + t) * NCLS + cls] = acc + bho[cls] + bro[cls];
        }
        __syncthreads();
    }
}

// ---------------- launch ----------------
extern "C" void kernel_launch(void* const* d_in, const int* in_sizes, int n_in,
                              void* d_out, int out_size) {
    const float* x    = (const float*)d_in[0];
    const float* Wkey = (const float*)d_in[1];
    const float* bkey = (const float*)d_in[2];
    const float* Wadd = (const float*)d_in[3];
    const float* badd = (const float*)d_in[4];
    const float* Wsig = (const float*)d_in[5];
    const float* bsig = (const float*)d_in[6];
    const float* Who  = (const float*)d_in[7];
    const float* bho  = (const float*)d_in[8];
    const float* Wro  = (const float*)d_in[9];
    const float* bro  = (const float*)d_in[10];
    const float* Wrh  = (const float*)d_in[11];
    const float* brh  = (const float*)d_in[12];
    const float* Wih  = (const float*)d_in[13];
    const float* bih  = (const float*)d_in[14];
    const float* Whh  = (const float*)d_in[15];
    const float* bhh  = (const float*)d_in[16];
    float* out = (float*)d_out;

    prep_weights<<<1000, 256>>>(Whh, Wkey, Wadd, Wrh);
    gemm_gates_x<<<dim3((G4H + GBN - 1) / GBN, B_ * T_ / GBM), 256>>>(x, Wih, bih);

    size_t shmem = 2 * sizeof(BS) + 3200 * 4 + (size_t)RD * H_ * 4;
    cudaFuncSetAttribute(mann_recurrent, cudaFuncAttributeMaxDynamicSharedMemorySize, (int)shmem);
    mann_recurrent<<<NBLK, THREADS, shmem>>>(bkey, badd, Wsig, bsig, Who, bho,
                                             Wro, bro, brh, bhh, out);
}